// round 1
// baseline (speedup 1.0000x reference)
#include <cuda_runtime.h>
#include <cuda_bf16.h>

// RBFEmbedding: out[b,i,d] = token_emb[an[b,i],d] + proj_b[d]
//                          + (1/N) * sum_j sum_k exp(-((d_ij - c_k)/w)^2) * W[k,d]
// B=16, N=512, K=50, D=256. Centers c_k = k*delta, delta = 12/49, w = 2*delta.
//
// Key math: with x = d/w, x_k = x - k/2:
//   rbf_{k+1} = rbf_k * g_k,  g_k = exp(x_k - 1/4),  g_{k+1} = g_k * exp(-1/2)
// Exact 2-FMUL-per-step recurrence. Started at k0 = clamp(round(d/delta)-8, 0, 34)
// over a 16-wide window (dropped terms <= exp(-14) ~ 8e-7). d clamped to 16 so
// g never overflows (worst g0 = exp(15.45)).

#define THREADS 128
#define R 16           // rows (i) per block
#define JG 8           // j-groups (THREADS / R)
#define JLEN 64        // 512 / JG
#define NS 50          // num RBF centers
#define WIN 16         // recurrence window

__global__ __launch_bounds__(THREADS)
void rbf_embed_kernel(const int* __restrict__ an,
                      const float* __restrict__ pos,
                      const float* __restrict__ tok,
                      const float* __restrict__ W,
                      const float* __restrict__ bias,
                      float* __restrict__ out)
{
    // smem: positions (SoA), transposed per-thread accumulators (conflict-free:
    // bank = tid mod 32 independent of k), reduced rbf means, atomic numbers.
    __shared__ float sx[512], sy[512], sz[512];
    __shared__ float sacc[NS][THREADS];   // [k][thread] -> 25600 B
    __shared__ float rbfm[NS][R];         // rbf_mean transposed [k][i]
    __shared__ int   an_s[R];

    const int tid = threadIdx.x;
    const int b   = blockIdx.y;
    const int i0  = blockIdx.x * R;

    // ---- load batch positions into smem (SoA) ----
    const float* pb = pos + (size_t)b * 512 * 3;
    for (int j = tid; j < 512; j += THREADS) {
        sx[j] = pb[j * 3 + 0];
        sy[j] = pb[j * 3 + 1];
        sz[j] = pb[j * 3 + 2];
    }
    if (tid < R) an_s[tid] = an[b * 512 + i0 + tid];
    // zero accumulators
    float* sacc_flat = &sacc[0][0];
    #pragma unroll
    for (int idx = 0; idx < NS; ++idx)
        sacc_flat[idx * THREADS + tid] = 0.0f;
    __syncthreads();

    const int r  = tid & (R - 1);
    const int jg = tid >> 4;             // 0..7
    const int i  = i0 + r;
    const float xi = sx[i], yi = sy[i], zi = sz[i];

    const float INV_DELTA = 49.0f / 12.0f;      // 1/delta
    const float MAGIC     = 12582912.0f;        // 1.5 * 2^23 (round-to-nearest)
    const float SQL2E     = 1.2011224087864498f;   // sqrt(log2 e)
    const float L2E       = 1.4426950408889634f;
    const float NQL2E     = -0.25f * 1.4426950408889634f;
    const float EM05      = 0.60653065971263342f;  // exp(-1/2)

    const int jbase = jg * JLEN;
    for (int jj = 0; jj < JLEN; ++jj) {
        const int j = jbase + jj;
        float dx = xi - sx[j];
        float dy = yi - sy[j];
        float dz = zi - sz[j];
        float dd = fmaf(dx, dx, fmaf(dy, dy, fmaf(dz, dz, 1e-8f)));
        float d;
        asm("sqrt.approx.f32 %0, %1;" : "=f"(d) : "f"(dd));
        d = fminf(d, 16.0f);                      // far pairs contribute <= 1e-29

        float t   = d * INV_DELTA;                // = d/delta, in [0, 65.4]
        float kf  = __fadd_rn(__fadd_rn(t, MAGIC), -MAGIC);   // rint(t)
        float k0f = fminf(fmaxf(kf - 8.0f, 0.0f), (float)(NS - WIN));
        int   k0  = (int)k0f;
        float x0  = 0.5f * (t - k0f);             // (d - k0*delta)/w

        // rr = exp(-x0^2), gg = exp(x0 - 0.25)
        float u  = x0 * SQL2E;
        float a0 = -u * u;
        float rr; asm("ex2.approx.f32 %0, %1;" : "=f"(rr) : "f"(a0));
        float ga = fmaf(x0, L2E, NQL2E);
        float gg; asm("ex2.approx.f32 %0, %1;" : "=f"(gg) : "f"(ga));

        float* ap = &sacc[k0][tid];
        #pragma unroll
        for (int tt = 0; tt < WIN; ++tt) {
            ap[tt * THREADS] += rr;   // conflict-free: bank = tid mod 32
            rr *= gg;
            gg *= EM05;
        }
    }
    __syncthreads();

    // ---- reduce the JG partial accumulators per (i, k); fold in 1/N ----
    for (int idx = tid; idx < NS * R; idx += THREADS) {
        const int k  = idx >> 4;       // idx / R
        const int ii = idx & (R - 1);
        float s = 0.0f;
        #pragma unroll
        for (int g2 = 0; g2 < JG; ++g2)
            s += sacc[k][g2 * R + ii];
        rbfm[k][ii] = s * (1.0f / 512.0f);
    }
    __syncthreads();

    // ---- epilogue: out[i,d] = bias[d] + tok[an[i],d] + sum_k rbfm[i,k]*W[k,d]
    for (int d0 = tid; d0 < 256; d0 += THREADS) {
        float acc[R];
        const float bd = __ldg(&bias[d0]);
        #pragma unroll
        for (int ii = 0; ii < R; ++ii)
            acc[ii] = bd + __ldg(&tok[an_s[ii] * 256 + d0]);

        #pragma unroll 5
        for (int k = 0; k < NS; ++k) {
            const float w = __ldg(&W[k * 256 + d0]);
            #pragma unroll
            for (int ii = 0; ii < R; ++ii)
                acc[ii] = fmaf(rbfm[k][ii], w, acc[ii]);
        }

        float* op = out + ((size_t)(b * 512 + i0)) * 256 + d0;
        #pragma unroll
        for (int ii = 0; ii < R; ++ii)
            op[ii * 256] = acc[ii];
    }
}

extern "C" void kernel_launch(void* const* d_in, const int* in_sizes, int n_in,
                              void* d_out, int out_size)
{
    const int*   an   = (const int*)  d_in[0];   // [B,512] int32
    const float* pos  = (const float*)d_in[1];   // [B,512,3] f32
    const float* tok  = (const float*)d_in[2];   // [100,256] f32
    const float* W    = (const float*)d_in[3];   // [50,256]  f32
    const float* bias = (const float*)d_in[4];   // [256]     f32

    const int B = in_sizes[0] / 512;             // 16
    dim3 grid(512 / R, B);
    rbf_embed_kernel<<<grid, THREADS>>>(an, pos, tok, W, bias, (float*)d_out);
}

// round 2
// speedup vs baseline: 1.1790x; 1.1790x over previous
#include <cuda_runtime.h>
#include <cuda_bf16.h>

// RBFEmbedding: out[b,i,d] = token_emb[an[b,i],d] + proj_b[d]
//                          + (1/N) * sum_j sum_k exp(-((d_ij - c_k)/w)^2) * W[k,d]
// B=16, N=512, K=50, D=256. Centers c_k = k*delta, delta = 12/49, w = 2*delta.
//
// Recurrence (exact): with x_m = x0 - m/2,  rbf_{m+1} = rbf_m * g_m,
//   g_m = exp(x_m - 1/4), g_{m+1} = g_m * e^{-1/2}.
// Packed double-step: (rbf_m, rbf_{m+1}) *= (g_m g_{m+1}, g_{m+1} g_{m+2}),
//   G-pair *= (e^-2, e^-2).  14-wide window, even-aligned so accumulators are
//   float2 (LDS.64/STS.64, conflict-free since bank = f(tid) only).

#define THREADS 128
#define R 16           // rows (i) per block
#define JG 8           // j-groups
#define JLEN 64        // 512 / JG
#define NS 50
#define KK 25          // 64-bit accumulator slots (2 k each)
#define WIN2 7         // 7 double-steps = window of 14 centers

typedef unsigned long long ull;

__device__ __forceinline__ ull pack2(float lo, float hi) {
    ull r; asm("mov.b64 %0, {%1, %2};" : "=l"(r) : "f"(lo), "f"(hi)); return r;
}
__device__ __forceinline__ void unpack2(ull v, float& lo, float& hi) {
    asm("mov.b64 {%0, %1}, %2;" : "=f"(lo), "=f"(hi) : "l"(v));
}
__device__ __forceinline__ ull add2(ull a, ull b) {
    ull r; asm("add.rn.f32x2 %0, %1, %2;" : "=l"(r) : "l"(a), "l"(b)); return r;
}
__device__ __forceinline__ ull mul2(ull a, ull b) {
    ull r; asm("mul.rn.f32x2 %0, %1, %2;" : "=l"(r) : "l"(a), "l"(b)); return r;
}
__device__ __forceinline__ ull fma2(ull a, ull b, ull c) {
    ull r; asm("fma.rn.f32x2 %0, %1, %2, %3;" : "=l"(r) : "l"(a), "l"(b), "l"(c)); return r;
}

__global__ __launch_bounds__(THREADS)
void rbf_embed_kernel(const int* __restrict__ an,
                      const float* __restrict__ pos,
                      const float* __restrict__ tok,
                      const float* __restrict__ W,
                      const float* __restrict__ bias,
                      float* __restrict__ out)
{
    __shared__ float sx[512], sy[512], sz[512];
    __shared__ ull  sacc2[KK][THREADS];   // 25.6 KB, [kk][thread], float2 per slot
    __shared__ ull  rbfm2[NS][R / 2];     // rbf means, float2 over ii-pairs
    __shared__ int  an_s[R];

    const int tid = threadIdx.x;
    const int b   = blockIdx.y;
    const int i0  = blockIdx.x * R;

    // ---- positions -> smem (SoA) ----
    const float* pb = pos + (size_t)b * 512 * 3;
    for (int j = tid; j < 512; j += THREADS) {
        sx[j] = pb[j * 3 + 0];
        sy[j] = pb[j * 3 + 1];
        sz[j] = pb[j * 3 + 2];
    }
    if (tid < R) an_s[tid] = an[b * 512 + i0 + tid];
    #pragma unroll
    for (int kk = 0; kk < KK; ++kk) sacc2[kk][tid] = 0ULL;
    __syncthreads();

    const int r  = tid & (R - 1);
    const int jg = tid >> 4;
    const float xi = sx[i0 + r], yi = sy[i0 + r], zi = sz[i0 + r];

    const float INV_DELTA = 49.0f / 12.0f;
    const float MAGIC     = 12582912.0f;                 // 1.5*2^23
    const float SQL2E     = 1.2011224087864498f;         // sqrt(log2 e)
    const float L2E       = 1.4426950408889634f;
    const float NQL2E     = -0.25f * 1.4426950408889634f;
    const float BETA      = 0.60653065971263342f;        // e^-1/2
    const float BETA2     = 0.36787944117144233f;        // e^-1
    const ull   B4        = pack2(0.13533528323661270f, 0.13533528323661270f); // e^-2

    const int jbase = jg * JLEN;
    #pragma unroll 2
    for (int jj = 0; jj < JLEN; ++jj) {
        const int j = jbase + jj;
        float dx = xi - sx[j];
        float dy = yi - sy[j];
        float dz = zi - sz[j];
        float dd = fmaf(dx, dx, fmaf(dy, dy, fmaf(dz, dz, 1e-8f)));
        float d;  asm("sqrt.approx.f32 %0, %1;" : "=f"(d) : "f"(dd));
        d = fminf(d, 16.0f);

        float t  = d * INV_DELTA;                      // d/delta in [0, 65.4]
        float hf = fmaf(t, 0.5f, -3.5f);               // (t-7)/2
        float hr = __fadd_rn(__fadd_rn(hf, MAGIC), -MAGIC);   // rint
        hr = fminf(fmaxf(hr, 0.0f), 18.0f);            // kk0 in [0,18] -> k0=2*hr
        const int kk0 = (int)hr;
        float x0 = fmaf(t, 0.5f, -hr);                 // (d - k0*delta)/w

        // rr0 = exp(-x0^2); g0 = exp(x0 - 1/4)
        float u  = x0 * SQL2E;
        float a0 = -(u * u);
        float rr0; asm("ex2.approx.f32 %0, %1;" : "=f"(rr0) : "f"(a0));
        float ga = fmaf(x0, L2E, NQL2E);
        float g0; asm("ex2.approx.f32 %0, %1;" : "=f"(g0) : "f"(ga));

        float g0sq = g0 * g0;
        float gA   = g0sq * BETA;        // g0*g1
        float gB   = gA * BETA2;         // g1*g2
        ull Gp  = pack2(gA, gB);
        ull rrp = pack2(rr0, rr0 * g0);  // (rbf_0, rbf_1)

        ull* ap = &sacc2[kk0][tid];
        #pragma unroll
        for (int tt = 0; tt < WIN2; ++tt) {
            ap[tt * THREADS] = add2(ap[tt * THREADS], rrp);
            rrp = mul2(rrp, Gp);
            Gp  = mul2(Gp, B4);
        }
    }
    __syncthreads();

    // ---- reduce JG partials per (k, ii), fold in 1/N ----
    for (int idx = tid; idx < NS * R; idx += THREADS) {
        const int k  = idx >> 4;
        const int ii = idx & (R - 1);
        const float* sf = (const float*)&sacc2[k >> 1][0];
        const int par = (k & 1);
        float s = 0.0f;
        #pragma unroll
        for (int g = 0; g < JG; ++g)
            s += sf[(g * R + ii) * 2 + par];
        ((float*)rbfm2)[k * R + ii] = s * (1.0f / 512.0f);
    }
    __syncthreads();

    // ---- epilogue: [16 x 50] @ [50 x 256] + bias + token gather ----
    // thread owns (d0, d0+128); acc packed over ii-pairs; rbfm loaded once per k.
    {
        const int d0 = tid;
        const float bd0 = __ldg(&bias[d0]);
        const float bd1 = __ldg(&bias[d0 + 128]);
        ull accA[8], accB[8];
        #pragma unroll
        for (int p = 0; p < 8; ++p) {
            const int ta = an_s[2 * p] * 256, tb = an_s[2 * p + 1] * 256;
            accA[p] = pack2(bd0 + __ldg(&tok[ta + d0]),       bd0 + __ldg(&tok[tb + d0]));
            accB[p] = pack2(bd1 + __ldg(&tok[ta + d0 + 128]), bd1 + __ldg(&tok[tb + d0 + 128]));
        }
        #pragma unroll 2
        for (int k = 0; k < NS; ++k) {
            const float wa = __ldg(&W[k * 256 + d0]);
            const float wb = __ldg(&W[k * 256 + d0 + 128]);
            const ull wpa = pack2(wa, wa);
            const ull wpb = pack2(wb, wb);
            const ull* rp = rbfm2[k];
            #pragma unroll
            for (int p = 0; p < 8; ++p) {
                const ull rv = rp[p];      // warp-uniform broadcast LDS.64
                accA[p] = fma2(rv, wpa, accA[p]);
                accB[p] = fma2(rv, wpb, accB[p]);
            }
        }
        float* op = out + ((size_t)(b * 512 + i0)) * 256 + d0;
        #pragma unroll
        for (int p = 0; p < 8; ++p) {
            float lo, hi;
            unpack2(accA[p], lo, hi);
            op[(2 * p) * 256]       = lo;
            op[(2 * p + 1) * 256]   = hi;
            unpack2(accB[p], lo, hi);
            op[(2 * p) * 256 + 128]     = lo;
            op[(2 * p + 1) * 256 + 128] = hi;
        }
    }
}

extern "C" void kernel_launch(void* const* d_in, const int* in_sizes, int n_in,
                              void* d_out, int out_size)
{
    const int*   an   = (const int*)  d_in[0];   // [B,512] int32
    const float* pos  = (const float*)d_in[1];   // [B,512,3] f32
    const float* tok  = (const float*)d_in[2];   // [100,256] f32
    const float* W    = (const float*)d_in[3];   // [50,256]  f32
    const float* bias = (const float*)d_in[4];   // [256]     f32

    const int B = in_sizes[0] / 512;             // 16
    dim3 grid(512 / R, B);
    rbf_embed_kernel<<<grid, THREADS>>>(an, pos, tok, W, bias, (float*)d_out);
}